// round 16
// baseline (speedup 1.0000x reference)
#include <cuda_runtime.h>
#include <math.h>

#define B_    1024
#define C1    22
#define T1    438
#define C2    20
#define T2    439
#define TPAD  452
#define DOUT  18
#define N1F   448512.0
#define N2F   449536.0f
#define LOG_RECT_EPS (-9.210340371976184f)
#define NSWEEP_V  6
#define NSWEEP_QK 4
#define NSWEEP2   5

// ---------------- scratch ----------------
__device__ float  g_sigP[B_*3*C2*152];   // patch-major; pads stay 0 (never written)
__device__ double g_mx[C1];
__device__ double g_mom[253];
__device__ float  g_stats2[2*C2];
__device__ float  g_weff[C2*C1*12];
__device__ float  g_csum[C2*13];
__device__ float  g_b2f[C2];

__global__ void zero_stats() {
    int t = threadIdx.x;
    if (t < C1) g_mx[t] = 0.0;
    if (t < 2*C2) g_stats2[t] = 0.f;
    for (int e = t; e < 253; e += 320) g_mom[e] = 0.0;
}

// packed f32x2 helpers (PTX >= 8.6, sm_100+)
#define PK2(d, lo, hi) asm("mov.b64 %0, {%1, %2};" : "=l"(d) : "f"(lo), "f"(hi))
#define UPK2(lo, hi, v) asm("mov.b64 {%0, %1}, %2;" : "=f"(lo), "=f"(hi) : "l"(v))
#define FMA2(d, a, b) asm("fma.rn.f32x2 %0, %1, %2, %0;" : "+l"(d) : "l"(a), "l"(b))

// ---------------- K0: x channel moments ----------------
__global__ __launch_bounds__(256) void k0(const float* __restrict__ x) {
    __shared__ float xp[C1*440];
    int b = blockIdx.x, tid = threadIdx.x;
    for (int e = tid; e < C1*440; e += 256) {
        int c = e / 440, tt = e % 440;
        xp[e] = (tt < T1) ? x[(b*C1 + c)*T1 + tt] : 0.f;
    }
    __syncthreads();
    for (int u = tid; u < 275; u += 256) {
        if (u < 253) {
            int i = 0, rem = u;
            while (rem >= C1 - i) { rem -= C1 - i; ++i; }
            int j = i + rem;
            const float4* ri = (const float4*)(xp + i*440);
            const float4* rj = (const float4*)(xp + j*440);
            float acc = 0.f;
#pragma unroll
            for (int t = 0; t < 110; ++t) {
                float4 a4 = ri[t], c4 = rj[t];
                acc += a4.x*c4.x + a4.y*c4.y + a4.z*c4.z + a4.w*c4.w;
            }
            atomicAdd(&g_mom[u], (double)acc);
        } else {
            int c = u - 253;
            float s = 0.f;
            const float* r = xp + c*440;
            for (int t = 0; t < T1; ++t) s += r[t];
            atomicAdd(&g_mx[c], (double)s);
        }
    }
}

// ---------------- KW: fold bn1 into conv weights (1 block) ----------------
__global__ __launch_bounds__(256) void kw(const float* __restrict__ w1,
                                          const float* __restrict__ b1,
                                          const float* __restrict__ g1,
                                          const float* __restrict__ be1,
                                          const float* __restrict__ w2,
                                          const float* __restrict__ b2) {
    __shared__ float s1[C1], t1[C1];
    __shared__ double mxs[C1];
    int tid = threadIdx.x;
    if (tid < C1) mxs[tid] = g_mx[tid] / N1F;
    __syncthreads();
    if (tid < C1) {
        int c = tid;
        double d = 0.0;
        for (int h = 0; h < C1; ++h) d += (double)w1[c*C1 + h] * mxs[h];
        double q = 0.0;
        for (int h = 0; h < C1; ++h) {
            double wh = (double)w1[c*C1 + h];
            for (int hp = 0; hp < C1; ++hp) {
                int a = h < hp ? h : hp, bb = h < hp ? hp : h;
                int idx = a*C1 - a*(a-1)/2 + (bb - a);
                double G = g_mom[idx] / N1F - mxs[h]*mxs[hp];
                q += wh * (double)w1[c*C1 + hp] * G;
            }
        }
        float s = (float)(rsqrt(q + 1e-5)) * g1[c];
        float mean1 = (float)d + b1[c];
        s1[c] = s;
        t1[c] = be1[c] - mean1 * s;
    }
    __syncthreads();
    for (int e = tid; e < C2*C1*12; e += 256) {
        int o = e / (C1*12), r = e % (C1*12);
        int h = r / 12, k = r % 12;
        float s = 0.f;
        for (int i = 0; i < C1; ++i)
            s = fmaf(w2[(o*C1 + i)*12 + k] * s1[i], w1[i*C1 + h], s);
        g_weff[(o*C1 + h)*12 + k] = s;
    }
    if (tid < C2) {
        int o = tid;
        float cs = 0.f;
        g_csum[o*13 + 0] = 0.f;
        for (int k = 0; k < 12; ++k) {
            float tb = 0.f;
            for (int i = 0; i < C1; ++i) tb = fmaf(w2[(o*C1 + i)*12 + k], t1[i], tb);
            cs += tb;
            g_csum[o*13 + k + 1] = cs;
        }
        g_b2f[o] = b2[o];
    }
}

// ---------------- K13: fused conv via packed f32x2 FMA + bn2 stats, patch-major out --------
__global__ __launch_bounds__(288) void k13(const float* __restrict__ x) {
    extern __shared__ float sm[];
    float* xp = sm;
    __shared__ float csumS[C2*13], sb2[C2], s2[2*C2];
    int b = blockIdx.x, tid = threadIdx.x;

    for (int e = tid; e < C2*13; e += 288) csumS[e] = g_csum[e];
    if (tid < C2) sb2[tid] = g_b2f[tid];
    if (tid < 2*C2) s2[tid] = 0.f;
    for (int e = tid; e < C1*TPAD; e += 288) {
        int c = e / TPAD, tt = e % TPAD, t = tt - 6;
        xp[e] = ((unsigned)t < (unsigned)T1) ? x[(b*C1 + c)*T1 + t] : 0.f;
    }
    __syncthreads();

    float* sigB = g_sigP + (size_t)b * 9120;
    for (int u = tid; u < 550; u += 288) {
        int og = u / 55, tb = u % 55, tp0 = tb*8;
        int o0 = og*2, o1 = og*2 + 1;
        // packed accumulators: positions (0,1)(2,3)(4,5)(6,7) per channel
        unsigned long long acc0[4], acc1[4];
#pragma unroll
        for (int m = 0; m < 4; ++m) { acc0[m] = 0ull; acc1[m] = 0ull; }
#pragma unroll 1
        for (int i = 0; i < C1; ++i) {
            float win[20];
            const float4* inr4 = (const float4*)(xp + i*TPAD + tp0);
#pragma unroll
            for (int m = 0; m < 5; ++m) {
                float4 v = inr4[m];
                win[4*m+0] = v.x; win[4*m+1] = v.y; win[4*m+2] = v.z; win[4*m+3] = v.w;
            }
            // even-aligned pairs pe[m]=(win[2m],win[2m+1]); odd po[m]=(win[2m+1],win[2m+2])
            unsigned long long pe[10], po[9];
#pragma unroll
            for (int m = 0; m < 10; ++m) PK2(pe[m], win[2*m], win[2*m+1]);
#pragma unroll
            for (int m = 0; m < 9; ++m) PK2(po[m], win[2*m+1], win[2*m+2]);

            float wf0[12], wf1[12];
            const float4* w40 = (const float4*)(g_weff + (o0*C1 + i)*12);
            const float4* w41 = (const float4*)(g_weff + (o1*C1 + i)*12);
#pragma unroll
            for (int m = 0; m < 3; ++m) {
                float4 v0 = __ldg(w40 + m), v1 = __ldg(w41 + m);
                wf0[4*m+0] = v0.x; wf0[4*m+1] = v0.y; wf0[4*m+2] = v0.z; wf0[4*m+3] = v0.w;
                wf1[4*m+0] = v1.x; wf1[4*m+1] = v1.y; wf1[4*m+2] = v1.z; wf1[4*m+3] = v1.w;
            }
#pragma unroll
            for (int k = 0; k < 12; ++k) {
                unsigned long long w0p, w1p;
                PK2(w0p, wf0[k], wf0[k]);
                PK2(w1p, wf1[k], wf1[k]);
                int a = k >> 1;
                if (k & 1) {
#pragma unroll
                    for (int m = 0; m < 4; ++m) {
                        FMA2(acc0[m], w0p, po[a+m]);
                        FMA2(acc1[m], w1p, po[a+m]);
                    }
                } else {
#pragma unroll
                    for (int m = 0; m < 4; ++m) {
                        FMA2(acc0[m], w0p, pe[a+m]);
                        FMA2(acc1[m], w1p, pe[a+m]);
                    }
                }
            }
        }
        float v0a[8], v1a[8];
#pragma unroll
        for (int m = 0; m < 4; ++m) {
            UPK2(v0a[2*m], v0a[2*m+1], acc0[m]);
            UPK2(v1a[2*m], v1a[2*m+1], acc1[m]);
        }
        float ls0 = 0.f, lq0 = 0.f, ls1 = 0.f, lq1 = 0.f;
#pragma unroll
        for (int j = 0; j < 8; ++j) {
            int tp = tp0 + j;
            if (tp < T2) {
                int kmin = 6 - tp; kmin = kmin < 0 ? 0 : kmin;
                int kmax = 443 - tp; kmax = kmax > 11 ? 11 : kmax;
                float v0 = v0a[j] + sb2[o0] + csumS[o0*13 + kmax + 1] - csumS[o0*13 + kmin];
                float v1 = v1a[j] + sb2[o1] + csumS[o1*13 + kmax + 1] - csumS[o1*13 + kmin];
                int p = (tp >= 147) + (tp >= 293);
                int col = tp - ((p == 0) ? 0 : (p == 1 ? 147 : 293));
                sigB[(p*20 + o0)*152 + col] = v0;
                sigB[(p*20 + o1)*152 + col] = v1;
                ls0 += v0; lq0 += v0*v0;
                ls1 += v1; lq1 += v1*v1;
            }
        }
        atomicAdd(&s2[o0], ls0);
        atomicAdd(&s2[C2+o0], lq0);
        atomicAdd(&s2[o1], ls1);
        atomicAdd(&s2[C2+o1], lq1);
    }
    __syncthreads();
    if (tid < 2*C2) atomicAdd(&g_stats2[tid], s2[tid]);
}

// ---------------- one-sided (Hestenes) Jacobi, columns in registers ----------------
__device__ __forceinline__ void jacobi1s(float b[18], const unsigned char* sched, int lane, int nsweep) {
#pragma unroll 1
    for (int sweep = 0; sweep < nsweep; ++sweep) {
#pragma unroll 1
        for (int r = 0; r < 17; ++r) {
            int partner = sched[r*32 + lane];
            float pb[18];
#pragma unroll
            for (int i = 0; i < 18; ++i) pb[i] = __shfl_sync(0xffffffffu, b[i], partner);
            float app = 0.f, apq = 0.f;
#pragma unroll
            for (int i = 0; i < 18; ++i) {
                app = fmaf(b[i], b[i], app);
                apq = fmaf(b[i], pb[i], apq);
            }
            float aqq = __shfl_sync(0xffffffffu, app, partner);
            bool lower = lane < partner;
            float dpp = lower ? app : aqq;
            float dqq = lower ? aqq : app;
            float c = 1.f, s = 0.f;
            if (fabsf(apq) > 1e-34f) {
                float theta = 0.5f*(dqq - dpp)/apq;
                float t = 1.f/(fabsf(theta) + sqrtf(fmaf(theta, theta, 1.f)));
                t = (theta < 0.f) ? -t : t;
                c = rsqrtf(fmaf(t, t, 1.f));
                s = t*c;
            }
            float sp = lower ? -s : s;
#pragma unroll
            for (int i = 0; i < 18; ++i) b[i] = fmaf(sp, pb[i], c*b[i]);
        }
    }
}

// smem float offsets (k45)
#define OFF_A     0
#define OFF_LOGS  6480
#define OFF_CM    9396
#define OFF_W3    10596
#define OFF_FEAT  11676
#define OFF_EN    12189
#define OFF_PROB  12198
#define OFF_S2    12207
#define OFF_MU    12227
#define OFF_MISC  12287
#define SMEM_FLOATS 12292
#define SMEM_BYTES  (SMEM_FLOATS*4 + 17*32 + 32)

// ---------------- K45: cov + QKV + 9 logm + attention + 3 eigh + feat + linear ----------------
__global__ __launch_bounds__(288, 4) void k45(const float* __restrict__ g2,
                                              const float* __restrict__ Wq,
                                              const float* __restrict__ Wk,
                                              const float* __restrict__ Wv,
                                              const float* __restrict__ lw,
                                              const float* __restrict__ lb,
                                              float* __restrict__ out) {
    extern __shared__ float sm[];
    float* sseg = sm + OFF_A;
    float* Cm   = sm + OFF_CM;
    float* W3   = sm + OFF_W3;
    float* feat = sm + OFF_FEAT;
    float* en   = sm + OFF_EN;
    float* prob = sm + OFF_PROB;
    float* s2s  = sm + OFF_S2;
    float* mu   = sm + OFF_MU;
    float* misc = sm + OFF_MISC;
    unsigned char* sched = (unsigned char*)(sm + SMEM_FLOATS);
    float* P    = sm + OFF_A;
    float* ES   = sm + OFF_A;
    float* logs = sm + OFF_LOGS;

    int b = blockIdx.x, tid = threadIdx.x;
    int w = tid >> 5, lane = tid & 31;

    if (tid == 0) {
        int a[18];
        for (int i = 0; i < 18; ++i) a[i] = i;
        for (int r = 0; r < 17; ++r) {
            for (int k = 0; k < 9; ++k) {
                int xx = a[k], yy = a[17-k];
                sched[r*32 + xx] = (unsigned char)yy;
                sched[r*32 + yy] = (unsigned char)xx;
            }
            for (int g = 18; g < 32; ++g) sched[r*32 + g] = (unsigned char)g;
            int last = a[17];
            for (int i = 17; i >= 2; --i) a[i] = a[i-1];
            a[1] = last;
        }
    }
    if (tid < C2) {
        float mn = g_stats2[tid] / N2F;
        float v  = g_stats2[C2+tid] / N2F - mn*mn;
        s2s[tid] = rsqrtf(v + 1e-5f) * g2[tid];
    }
    for (int e = tid; e < C2*DOUT; e += 288) {
        W3[0*360 + e] = Wq[e]; W3[1*360 + e] = Wk[e]; W3[2*360 + e] = Wv[e];
    }
    {
        const float4* src = (const float4*)(g_sigP + (size_t)b * 9120);
        float4* dst = (float4*)sseg;
        for (int e = tid; e < 2280; e += 288) dst[e] = src[e];
    }
    __syncthreads();
    for (int row = w; row < 60; row += 9) {
        int p = row / 20, L = (p == 0) ? 147 : 146;
        float s = 0.f;
        for (int t = lane; t < 152; t += 32) s += sseg[row*152 + t];
#pragma unroll
        for (int off = 16; off; off >>= 1) s += __shfl_xor_sync(0xffffffffu, s, off);
        if (lane == 0) mu[row] = s / (float)L;
    }
    __syncthreads();
    for (int e = tid; e < 60*152; e += 288) {
        int row = e / 152, col = e % 152;
        int p = row / 20, L = (p == 0) ? 147 : 146;
        if (col < L) sseg[e] -= mu[row];
    }
    __syncthreads();

    for (int u = tid; u < 165; u += 288) {
        int p = u / 55, s = u % 55;
        int I = 0, rem = s;
        while (rem >= 10 - I) { rem -= 10 - I; ++I; }
        int J = I + rem;
        int i0 = 2*I, i1 = 2*I + 1, j0 = 2*J, j1 = 2*J + 1;
        const float4* a0 = (const float4*)(sseg + (p*20 + i0)*152);
        const float4* a1 = (const float4*)(sseg + (p*20 + i1)*152);
        const float4* b0 = (const float4*)(sseg + (p*20 + j0)*152);
        const float4* b1 = (const float4*)(sseg + (p*20 + j1)*152);
        float s00 = 0.f, s01 = 0.f, s10 = 0.f, s11 = 0.f;
#pragma unroll
        for (int t = 0; t < 38; ++t) {
            float4 A0 = a0[t], A1 = a1[t], B0 = b0[t], B1 = b1[t];
            s00 += A0.x*B0.x + A0.y*B0.y + A0.z*B0.z + A0.w*B0.w;
            s01 += A0.x*B1.x + A0.y*B1.y + A0.z*B1.z + A0.w*B1.w;
            s10 += A1.x*B0.x + A1.y*B0.y + A1.z*B0.z + A1.w*B0.w;
            s11 += A1.x*B1.x + A1.y*B1.y + A1.z*B1.z + A1.w*B1.w;
        }
        float* Cp = Cm + p*400;
        float v00 = s00 * s2s[i0]*s2s[j0];
        float v01 = s01 * s2s[i0]*s2s[j1];
        float v10 = s10 * s2s[i1]*s2s[j0];
        float v11 = s11 * s2s[i1]*s2s[j1];
        Cp[i0*20 + j0] = v00; Cp[j0*20 + i0] = v00;
        Cp[i0*20 + j1] = v01; Cp[j1*20 + i0] = v01;
        Cp[i1*20 + j0] = v10; Cp[j0*20 + i1] = v10;
        Cp[i1*20 + j1] = v11; Cp[j1*20 + i1] = v11;
    }
    __syncthreads();
    if (tid < 3) {
        float tr = 0.f;
        for (int d = 0; d < C2; ++d) tr += Cm[tid*400 + d*21];
        misc[tid] = 1.f / tr;
    }
    __syncthreads();
    for (int e = tid; e < 3*400; e += 288) {
        int p = e / 400, r = e % 400;
        float v = Cm[e] * misc[p];
        if (r / 20 == r % 20) v += 1e-5f;
        Cm[e] = v;
    }
    __syncthreads();

    int pp_ = w / 3, xx_ = w % 3;
    for (int e = lane; e < 360; e += 32) {
        int a = e / 18, j = e % 18;
        float s = 0.f;
        const float* crow = Cm + pp_*400 + a*20;
        const float* wcol = W3 + xx_*360;
        for (int c = 0; c < C2; ++c) s = fmaf(crow[c], wcol[c*18 + j], s);
        P[w*360 + e] = s;
    }
    __syncwarp();
    float bcol[18];
#pragma unroll
    for (int i = 0; i < 18; ++i) bcol[i] = 0.f;
    if (lane < 18) {
        const float* Pw = P + w*360;
        const float* Wx = W3 + xx_*360;
#pragma unroll 1
        for (int i = 0; i < 18; ++i) {
            float s = 0.f;
            for (int a = 0; a < C2; ++a) s = fmaf(Wx[a*18 + i], Pw[a*18 + lane], s);
            bcol[i] = s;
        }
    }
    __syncthreads();

    jacobi1s(bcol, sched, lane, (xx_ == 2) ? NSWEEP_V : NSWEEP_QK);

    {
        float app = 0.f;
#pragma unroll
        for (int i = 0; i < 18; ++i) app = fmaf(bcol[i], bcol[i], app);
        float* St = ES + w*720;
        float* Bt = St + 360;
        if (lane < 18) {
            float lg = 0.5f * logf(fmaxf(app, 1e-38f));
            float coef = lg / app;
#pragma unroll
            for (int i = 0; i < 18; ++i) { St[i*20 + lane] = coef*bcol[i]; Bt[i*20 + lane] = bcol[i]; }
        }
        __syncwarp();
        for (int e = lane; e < 324; e += 32) {
            int i = e / 18, j = e % 18;
            const float4* Si = (const float4*)(St + i*20);
            const float4* Bj = (const float4*)(Bt + j*20);
            float s = 0.f;
#pragma unroll
            for (int m = 0; m < 4; ++m) {
                float4 a4 = Si[m], c4 = Bj[m];
                s += a4.x*c4.x + a4.y*c4.y + a4.z*c4.z + a4.w*c4.w;
            }
            s += St[i*20+16]*Bt[j*20+16] + St[i*20+17]*Bt[j*20+17];
            logs[w*324 + e] = s;
        }
    }
    __syncthreads();

    {
        int iK = w / 3, jQ = w % 3;
        const float* LK = logs + (iK*3 + 1)*324;
        const float* LQ = logs + (jQ*3 + 0)*324;
        float acc = 0.f;
        for (int e = lane; e < 324; e += 32) {
            float d = LK[e] - LQ[e];
            acc = fmaf(d, d, acc);
        }
#pragma unroll
        for (int off = 16; off; off >>= 1) acc += __shfl_xor_sync(0xffffffffu, acc, off);
        if (lane == 0) en[iK*3 + jQ] = acc;
    }
    __syncthreads();
    if (tid == 0) {
        float f[9];
        for (int e = 0; e < 9; ++e) f[e] = 1.f / (1.f + log1pf(en[e]));
        for (int p = 0; p < 3; ++p) {
            float f0 = f[0*3+p], f1 = f[1*3+p], f2 = f[2*3+p];
            float mx = fmaxf(f0, fmaxf(f1, f2));
            float e0 = expf(f0-mx), e1 = expf(f1-mx), e2 = expf(f2-mx);
            float inv = 1.f / (e0 + e1 + e2);
            prob[p*3+0] = e0*inv; prob[p*3+1] = e1*inv; prob[p*3+2] = e2*inv;
        }
    }
    __syncthreads();

    if (w < 3) {
        float p0 = prob[w*3+0], p1 = prob[w*3+1], p2 = prob[w*3+2];
#pragma unroll
        for (int i = 0; i < 18; ++i) bcol[i] = 0.f;
        if (lane < 18) {
            const float* V0 = logs + 2*324;
            const float* V1 = logs + 5*324;
            const float* V2 = logs + 8*324;
#pragma unroll
            for (int i = 0; i < 18; ++i) {
                int e = i*18 + lane;
                bcol[i] = p0*V0[e] + p1*V1[e] + p2*V2[e];
            }
        }
        float bound = 1e30f;
        if (lane < 18) {
            float rs = 0.f;
#pragma unroll
            for (int i = 0; i < 18; ++i) rs += fabsf(bcol[i]);
            float dg = bcol[lane];
            bound = dg - (rs - fabsf(dg));
        }
#pragma unroll
        for (int off = 16; off; off >>= 1) bound = fminf(bound, __shfl_xor_sync(0xffffffffu, bound, off));
        float alpha = fmaxf(0.f, -bound) + 1.0f;
        if (lane < 18) bcol[lane] += alpha;

        jacobi1s(bcol, sched, lane, NSWEEP2);

        float app = 0.f;
#pragma unroll
        for (int i = 0; i < 18; ++i) app = fmaf(bcol[i], bcol[i], app);
        float* St = ES + w*720;
        float* Bt = St + 360;
        if (lane < 18) {
            float lamS = sqrtf(app);
            float ev = fmaxf(lamS - alpha, LOG_RECT_EPS);
            float coef = ev / fmaxf(app, 1e-38f);
#pragma unroll
            for (int i = 0; i < 18; ++i) { St[i*20 + lane] = coef*bcol[i]; Bt[i*20 + lane] = bcol[i]; }
        }
        __syncwarp();
        for (int e = lane; e < 171; e += 32) {
            int i = 0, rem = e;
            while (rem >= 18 - i) { rem -= 18 - i; ++i; }
            int j = i + rem;
            const float4* Si = (const float4*)(St + i*20);
            const float4* Bj = (const float4*)(Bt + j*20);
            float s = 0.f;
#pragma unroll
            for (int m = 0; m < 4; ++m) {
                float4 a4 = Si[m], c4 = Bj[m];
                s += a4.x*c4.x + a4.y*c4.y + a4.z*c4.z + a4.w*c4.w;
            }
            s += St[i*20+16]*Bt[j*20+16] + St[i*20+17]*Bt[j*20+17];
            feat[w*171 + e] = s;
        }
    }
    __syncthreads();

    if (w < 4) {
        float acc = 0.f;
        for (int f = lane; f < 513; f += 32) acc = fmaf(lw[w*513 + f], feat[f], acc);
#pragma unroll
        for (int off = 16; off; off >>= 1) acc += __shfl_xor_sync(0xffffffffu, acc, off);
        if (lane == 0) out[b*4 + w] = acc + lb[w];
    }
}

// ---------------- launcher ----------------
extern "C" void kernel_launch(void* const* d_in, const int* in_sizes, int n_in,
                              void* d_out, int out_size) {
    const float* x   = (const float*)d_in[0];
    const float* w1  = (const float*)d_in[1];
    const float* b1  = (const float*)d_in[2];
    const float* g1  = (const float*)d_in[3];
    const float* be1 = (const float*)d_in[4];
    const float* w2  = (const float*)d_in[5];
    const float* b2  = (const float*)d_in[6];
    const float* g2  = (const float*)d_in[7];
    const float* Wq  = (const float*)d_in[9];
    const float* Wk  = (const float*)d_in[10];
    const float* Wv  = (const float*)d_in[11];
    const float* lw  = (const float*)d_in[12];
    const float* lb  = (const float*)d_in[13];

    size_t smem13 = (size_t)(C1*TPAD) * sizeof(float);
    cudaFuncSetAttribute(k13, cudaFuncAttributeMaxDynamicSharedMemorySize, (int)smem13);
    cudaFuncSetAttribute(k45, cudaFuncAttributeMaxDynamicSharedMemorySize, SMEM_BYTES);

    zero_stats<<<1, 320>>>();
    k0<<<B_, 256>>>(x);
    kw<<<1, 256>>>(w1, b1, g1, be1, w2, b2);
    k13<<<B_, 288, smem13>>>(x);
    k45<<<B_, 288, SMEM_BYTES>>>(g2, Wq, Wk, Wv, lw, lb, (float*)d_out);
}

// round 17
// speedup vs baseline: 1.0213x; 1.0213x over previous
#include <cuda_runtime.h>
#include <math.h>

#define B_    1024
#define C1    22
#define T1    438
#define C2    20
#define T2    439
#define TPAD  452
#define DOUT  18
#define N1F   448512.0
#define N2F   449536.0f
#define LOG_RECT_EPS (-9.210340371976184f)
#define NSWEEP_V  6
#define NSWEEP_QK 4
#define NSWEEP2   5

// ---------------- scratch ----------------
__device__ float  g_sigP[B_*3*C2*152];   // patch-major; pads stay 0 (never written)
__device__ float  g_momP[253*B_];        // per-block moment partials, column-major
__device__ float  g_mxP[C1*B_];
__device__ double g_mx[C1];
__device__ double g_mom[253];
__device__ float  g_stats2[2*C2];
__device__ float  g_weff[C2*C1*12];
__device__ float  g_csum[C2*13];
__device__ float  g_b2f[C2];

// ---------------- K0: x channel moment partials (no atomics) ----------------
__global__ __launch_bounds__(256) void k0(const float* __restrict__ x) {
    __shared__ float xp[C1*440];
    int b = blockIdx.x, tid = threadIdx.x;
    if (b == 0 && tid < 2*C2) g_stats2[tid] = 0.f;   // k13 runs strictly later
    for (int e = tid; e < C1*440; e += 256) {
        int c = e / 440, tt = e % 440;
        xp[e] = (tt < T1) ? x[(b*C1 + c)*T1 + tt] : 0.f;
    }
    __syncthreads();
    for (int u = tid; u < 275; u += 256) {
        if (u < 253) {
            int i = 0, rem = u;
            while (rem >= C1 - i) { rem -= C1 - i; ++i; }
            int j = i + rem;
            const float4* ri = (const float4*)(xp + i*440);
            const float4* rj = (const float4*)(xp + j*440);
            float acc = 0.f;
#pragma unroll
            for (int t = 0; t < 110; ++t) {
                float4 a4 = ri[t], c4 = rj[t];
                acc += a4.x*c4.x + a4.y*c4.y + a4.z*c4.z + a4.w*c4.w;
            }
            g_momP[u*B_ + b] = acc;
        } else {
            int c = u - 253;
            float s = 0.f;
            const float* r = xp + c*440;
            for (int t = 0; t < T1; ++t) s += r[t];
            g_mxP[c*B_ + b] = s;
        }
    }
}

// ---------------- KRED: column reduction of partials (275 blocks) ----------------
__global__ __launch_bounds__(256) void kred() {
    __shared__ double red[256];
    int u = blockIdx.x, tid = threadIdx.x;
    const float* col = (u < 253) ? (g_momP + u*B_) : (g_mxP + (u - 253)*B_);
    double s = 0.0;
#pragma unroll
    for (int t = tid; t < B_; t += 256) s += (double)col[t];
    red[tid] = s;
    __syncthreads();
    for (int off = 128; off; off >>= 1) {
        if (tid < off) red[tid] += red[tid + off];
        __syncthreads();
    }
    if (tid == 0) {
        if (u < 253) g_mom[u] = red[0];
        else g_mx[u - 253] = red[0];
    }
}

// ---------------- KW: fold bn1 into conv weights (1 block) ----------------
__global__ __launch_bounds__(256) void kw(const float* __restrict__ w1,
                                          const float* __restrict__ b1,
                                          const float* __restrict__ g1,
                                          const float* __restrict__ be1,
                                          const float* __restrict__ w2,
                                          const float* __restrict__ b2) {
    __shared__ float s1[C1], t1[C1];
    __shared__ double mxs[C1];
    int tid = threadIdx.x;
    if (tid < C1) mxs[tid] = g_mx[tid] / N1F;
    __syncthreads();
    if (tid < C1) {
        int c = tid;
        double d = 0.0;
        for (int h = 0; h < C1; ++h) d += (double)w1[c*C1 + h] * mxs[h];
        double q = 0.0;
        for (int h = 0; h < C1; ++h) {
            double wh = (double)w1[c*C1 + h];
            for (int hp = 0; hp < C1; ++hp) {
                int a = h < hp ? h : hp, bb = h < hp ? hp : h;
                int idx = a*C1 - a*(a-1)/2 + (bb - a);
                double G = g_mom[idx] / N1F - mxs[h]*mxs[hp];
                q += wh * (double)w1[c*C1 + hp] * G;
            }
        }
        float s = (float)(rsqrt(q + 1e-5)) * g1[c];
        float mean1 = (float)d + b1[c];
        s1[c] = s;
        t1[c] = be1[c] - mean1 * s;
    }
    __syncthreads();
    for (int e = tid; e < C2*C1*12; e += 256) {
        int o = e / (C1*12), r = e % (C1*12);
        int h = r / 12, k = r % 12;
        float s = 0.f;
        for (int i = 0; i < C1; ++i)
            s = fmaf(w2[(o*C1 + i)*12 + k] * s1[i], w1[i*C1 + h], s);
        g_weff[(o*C1 + h)*12 + k] = s;
    }
    if (tid < C2) {
        int o = tid;
        float cs = 0.f;
        g_csum[o*13 + 0] = 0.f;
        for (int k = 0; k < 12; ++k) {
            float tb = 0.f;
            for (int i = 0; i < C1; ++i) tb = fmaf(w2[(o*C1 + i)*12 + k], t1[i], tb);
            cs += tb;
            g_csum[o*13 + k + 1] = cs;
        }
        g_b2f[o] = b2[o];
    }
}

// ---------------- K13: fused conv (R15 scalar version) + bn2 stats, patch-major out --------
__global__ __launch_bounds__(288) void k13(const float* __restrict__ x) {
    extern __shared__ float sm[];
    float* xp = sm;
    __shared__ float csumS[C2*13], sb2[C2], s2[2*C2];
    int b = blockIdx.x, tid = threadIdx.x;

    for (int e = tid; e < C2*13; e += 288) csumS[e] = g_csum[e];
    if (tid < C2) sb2[tid] = g_b2f[tid];
    if (tid < 2*C2) s2[tid] = 0.f;
    for (int e = tid; e < C1*TPAD; e += 288) {
        int c = e / TPAD, tt = e % TPAD, t = tt - 6;
        xp[e] = ((unsigned)t < (unsigned)T1) ? x[(b*C1 + c)*T1 + t] : 0.f;
    }
    __syncthreads();

    float* sigB = g_sigP + (size_t)b * 9120;
    for (int u = tid; u < 550; u += 288) {
        int og = u / 55, tb = u % 55, tp0 = tb*8;
        int o0 = og*2, o1 = og*2 + 1;
        float acc0[8], acc1[8];
#pragma unroll
        for (int j = 0; j < 8; ++j) { acc0[j] = 0.f; acc1[j] = 0.f; }
#pragma unroll 1
        for (int i = 0; i < C1; ++i) {
            float win[20];
            const float4* inr4 = (const float4*)(xp + i*TPAD + tp0);
#pragma unroll
            for (int m = 0; m < 5; ++m) {
                float4 v = inr4[m];
                win[4*m+0] = v.x; win[4*m+1] = v.y; win[4*m+2] = v.z; win[4*m+3] = v.w;
            }
            float wf0[12], wf1[12];
            const float4* w40 = (const float4*)(g_weff + (o0*C1 + i)*12);
            const float4* w41 = (const float4*)(g_weff + (o1*C1 + i)*12);
#pragma unroll
            for (int m = 0; m < 3; ++m) {
                float4 v0 = __ldg(w40 + m), v1 = __ldg(w41 + m);
                wf0[4*m+0] = v0.x; wf0[4*m+1] = v0.y; wf0[4*m+2] = v0.z; wf0[4*m+3] = v0.w;
                wf1[4*m+0] = v1.x; wf1[4*m+1] = v1.y; wf1[4*m+2] = v1.z; wf1[4*m+3] = v1.w;
            }
#pragma unroll
            for (int k = 0; k < 12; ++k) {
#pragma unroll
                for (int j = 0; j < 8; ++j) {
                    acc0[j] = fmaf(wf0[k], win[k+j], acc0[j]);
                    acc1[j] = fmaf(wf1[k], win[k+j], acc1[j]);
                }
            }
        }
        float ls0 = 0.f, lq0 = 0.f, ls1 = 0.f, lq1 = 0.f;
#pragma unroll
        for (int j = 0; j < 8; ++j) {
            int tp = tp0 + j;
            if (tp < T2) {
                int kmin = 6 - tp; kmin = kmin < 0 ? 0 : kmin;
                int kmax = 443 - tp; kmax = kmax > 11 ? 11 : kmax;
                float v0 = acc0[j] + sb2[o0] + csumS[o0*13 + kmax + 1] - csumS[o0*13 + kmin];
                float v1 = acc1[j] + sb2[o1] + csumS[o1*13 + kmax + 1] - csumS[o1*13 + kmin];
                int p = (tp >= 147) + (tp >= 293);
                int col = tp - ((p == 0) ? 0 : (p == 1 ? 147 : 293));
                sigB[(p*20 + o0)*152 + col] = v0;
                sigB[(p*20 + o1)*152 + col] = v1;
                ls0 += v0; lq0 += v0*v0;
                ls1 += v1; lq1 += v1*v1;
            }
        }
        atomicAdd(&s2[o0], ls0);
        atomicAdd(&s2[C2+o0], lq0);
        atomicAdd(&s2[o1], ls1);
        atomicAdd(&s2[C2+o1], lq1);
    }
    __syncthreads();
    if (tid < 2*C2) atomicAdd(&g_stats2[tid], s2[tid]);
}

// ---------------- one-sided (Hestenes) Jacobi, columns in registers ----------------
__device__ __forceinline__ void jacobi1s(float b[18], const unsigned char* sched, int lane, int nsweep) {
#pragma unroll 1
    for (int sweep = 0; sweep < nsweep; ++sweep) {
#pragma unroll 1
        for (int r = 0; r < 17; ++r) {
            int partner = sched[r*32 + lane];
            float pb[18];
#pragma unroll
            for (int i = 0; i < 18; ++i) pb[i] = __shfl_sync(0xffffffffu, b[i], partner);
            float app = 0.f, apq = 0.f;
#pragma unroll
            for (int i = 0; i < 18; ++i) {
                app = fmaf(b[i], b[i], app);
                apq = fmaf(b[i], pb[i], apq);
            }
            float aqq = __shfl_sync(0xffffffffu, app, partner);
            bool lower = lane < partner;
            float dpp = lower ? app : aqq;
            float dqq = lower ? aqq : app;
            float c = 1.f, s = 0.f;
            if (fabsf(apq) > 1e-34f) {
                float theta = 0.5f*(dqq - dpp)/apq;
                float t = 1.f/(fabsf(theta) + sqrtf(fmaf(theta, theta, 1.f)));
                t = (theta < 0.f) ? -t : t;
                c = rsqrtf(fmaf(t, t, 1.f));
                s = t*c;
            }
            float sp = lower ? -s : s;
#pragma unroll
            for (int i = 0; i < 18; ++i) b[i] = fmaf(sp, pb[i], c*b[i]);
        }
    }
}

// smem float offsets (k45)
#define OFF_A     0
#define OFF_LOGS  6480
#define OFF_CM    9396
#define OFF_W3    10596
#define OFF_FEAT  11676
#define OFF_EN    12189
#define OFF_PROB  12198
#define OFF_S2    12207
#define OFF_MU    12227
#define OFF_MISC  12287
#define SMEM_FLOATS 12292
#define SMEM_BYTES  (SMEM_FLOATS*4 + 17*32 + 32)

// ---------------- K45: cov + QKV + 9 logm + attention + 3 eigh + feat + linear ----------------
__global__ __launch_bounds__(288, 4) void k45(const float* __restrict__ g2,
                                              const float* __restrict__ Wq,
                                              const float* __restrict__ Wk,
                                              const float* __restrict__ Wv,
                                              const float* __restrict__ lw,
                                              const float* __restrict__ lb,
                                              float* __restrict__ out) {
    extern __shared__ float sm[];
    float* sseg = sm + OFF_A;
    float* Cm   = sm + OFF_CM;
    float* W3   = sm + OFF_W3;
    float* feat = sm + OFF_FEAT;
    float* en   = sm + OFF_EN;
    float* prob = sm + OFF_PROB;
    float* s2s  = sm + OFF_S2;
    float* mu   = sm + OFF_MU;
    float* misc = sm + OFF_MISC;
    unsigned char* sched = (unsigned char*)(sm + SMEM_FLOATS);
    float* P    = sm + OFF_A;
    float* ES   = sm + OFF_A;
    float* logs = sm + OFF_LOGS;

    int b = blockIdx.x, tid = threadIdx.x;
    int w = tid >> 5, lane = tid & 31;

    if (tid == 0) {
        int a[18];
        for (int i = 0; i < 18; ++i) a[i] = i;
        for (int r = 0; r < 17; ++r) {
            for (int k = 0; k < 9; ++k) {
                int xx = a[k], yy = a[17-k];
                sched[r*32 + xx] = (unsigned char)yy;
                sched[r*32 + yy] = (unsigned char)xx;
            }
            for (int g = 18; g < 32; ++g) sched[r*32 + g] = (unsigned char)g;
            int last = a[17];
            for (int i = 17; i >= 2; --i) a[i] = a[i-1];
            a[1] = last;
        }
    }
    if (tid < C2) {
        float mn = g_stats2[tid] / N2F;
        float v  = g_stats2[C2+tid] / N2F - mn*mn;
        s2s[tid] = rsqrtf(v + 1e-5f) * g2[tid];
    }
    for (int e = tid; e < C2*DOUT; e += 288) {
        W3[0*360 + e] = Wq[e]; W3[1*360 + e] = Wk[e]; W3[2*360 + e] = Wv[e];
    }
    {
        const float4* src = (const float4*)(g_sigP + (size_t)b * 9120);
        float4* dst = (float4*)sseg;
        for (int e = tid; e < 2280; e += 288) dst[e] = src[e];
    }
    __syncthreads();
    for (int row = w; row < 60; row += 9) {
        int p = row / 20, L = (p == 0) ? 147 : 146;
        float s = 0.f;
        for (int t = lane; t < 152; t += 32) s += sseg[row*152 + t];
#pragma unroll
        for (int off = 16; off; off >>= 1) s += __shfl_xor_sync(0xffffffffu, s, off);
        if (lane == 0) mu[row] = s / (float)L;
    }
    __syncthreads();
    for (int e = tid; e < 60*152; e += 288) {
        int row = e / 152, col = e % 152;
        int p = row / 20, L = (p == 0) ? 147 : 146;
        if (col < L) sseg[e] -= mu[row];
    }
    __syncthreads();

    for (int u = tid; u < 165; u += 288) {
        int p = u / 55, s = u % 55;
        int I = 0, rem = s;
        while (rem >= 10 - I) { rem -= 10 - I; ++I; }
        int J = I + rem;
        int i0 = 2*I, i1 = 2*I + 1, j0 = 2*J, j1 = 2*J + 1;
        const float4* a0 = (const float4*)(sseg + (p*20 + i0)*152);
        const float4* a1 = (const float4*)(sseg + (p*20 + i1)*152);
        const float4* b0 = (const float4*)(sseg + (p*20 + j0)*152);
        const float4* b1 = (const float4*)(sseg + (p*20 + j1)*152);
        float s00 = 0.f, s01 = 0.f, s10 = 0.f, s11 = 0.f;
#pragma unroll
        for (int t = 0; t < 38; ++t) {
            float4 A0 = a0[t], A1 = a1[t], B0 = b0[t], B1 = b1[t];
            s00 += A0.x*B0.x + A0.y*B0.y + A0.z*B0.z + A0.w*B0.w;
            s01 += A0.x*B1.x + A0.y*B1.y + A0.z*B1.z + A0.w*B1.w;
            s10 += A1.x*B0.x + A1.y*B0.y + A1.z*B0.z + A1.w*B0.w;
            s11 += A1.x*B1.x + A1.y*B1.y + A1.z*B1.z + A1.w*B1.w;
        }
        float* Cp = Cm + p*400;
        float v00 = s00 * s2s[i0]*s2s[j0];
        float v01 = s01 * s2s[i0]*s2s[j1];
        float v10 = s10 * s2s[i1]*s2s[j0];
        float v11 = s11 * s2s[i1]*s2s[j1];
        Cp[i0*20 + j0] = v00; Cp[j0*20 + i0] = v00;
        Cp[i0*20 + j1] = v01; Cp[j1*20 + i0] = v01;
        Cp[i1*20 + j0] = v10; Cp[j0*20 + i1] = v10;
        Cp[i1*20 + j1] = v11; Cp[j1*20 + i1] = v11;
    }
    __syncthreads();
    if (tid < 3) {
        float tr = 0.f;
        for (int d = 0; d < C2; ++d) tr += Cm[tid*400 + d*21];
        misc[tid] = 1.f / tr;
    }
    __syncthreads();
    for (int e = tid; e < 3*400; e += 288) {
        int p = e / 400, r = e % 400;
        float v = Cm[e] * misc[p];
        if (r / 20 == r % 20) v += 1e-5f;
        Cm[e] = v;
    }
    __syncthreads();

    int pp_ = w / 3, xx_ = w % 3;
    for (int e = lane; e < 360; e += 32) {
        int a = e / 18, j = e % 18;
        float s = 0.f;
        const float* crow = Cm + pp_*400 + a*20;
        const float* wcol = W3 + xx_*360;
        for (int c = 0; c < C2; ++c) s = fmaf(crow[c], wcol[c*18 + j], s);
        P[w*360 + e] = s;
    }
    __syncwarp();
    float bcol[18];
#pragma unroll
    for (int i = 0; i < 18; ++i) bcol[i] = 0.f;
    if (lane < 18) {
        const float* Pw = P + w*360;
        const float* Wx = W3 + xx_*360;
#pragma unroll 1
        for (int i = 0; i < 18; ++i) {
            float s = 0.f;
            for (int a = 0; a < C2; ++a) s = fmaf(Wx[a*18 + i], Pw[a*18 + lane], s);
            bcol[i] = s;
        }
    }
    __syncthreads();

    jacobi1s(bcol, sched, lane, (xx_ == 2) ? NSWEEP_V : NSWEEP_QK);

    {
        float app = 0.f;
#pragma unroll
        for (int i = 0; i < 18; ++i) app = fmaf(bcol[i], bcol[i], app);
        float* St = ES + w*720;
        float* Bt = St + 360;
        if (lane < 18) {
            float lg = 0.5f * logf(fmaxf(app, 1e-38f));
            float coef = lg / app;
#pragma unroll
            for (int i = 0; i < 18; ++i) { St[i*20 + lane] = coef*bcol[i]; Bt[i*20 + lane] = bcol[i]; }
        }
        __syncwarp();
        for (int e = lane; e < 324; e += 32) {
            int i = e / 18, j = e % 18;
            const float4* Si = (const float4*)(St + i*20);
            const float4* Bj = (const float4*)(Bt + j*20);
            float s = 0.f;
#pragma unroll
            for (int m = 0; m < 4; ++m) {
                float4 a4 = Si[m], c4 = Bj[m];
                s += a4.x*c4.x + a4.y*c4.y + a4.z*c4.z + a4.w*c4.w;
            }
            s += St[i*20+16]*Bt[j*20+16] + St[i*20+17]*Bt[j*20+17];
            logs[w*324 + e] = s;
        }
    }
    __syncthreads();

    {
        int iK = w / 3, jQ = w % 3;
        const float* LK = logs + (iK*3 + 1)*324;
        const float* LQ = logs + (jQ*3 + 0)*324;
        float acc = 0.f;
        for (int e = lane; e < 324; e += 32) {
            float d = LK[e] - LQ[e];
            acc = fmaf(d, d, acc);
        }
#pragma unroll
        for (int off = 16; off; off >>= 1) acc += __shfl_xor_sync(0xffffffffu, acc, off);
        if (lane == 0) en[iK*3 + jQ] = acc;
    }
    __syncthreads();
    if (tid == 0) {
        float f[9];
        for (int e = 0; e < 9; ++e) f[e] = 1.f / (1.f + log1pf(en[e]));
        for (int p = 0; p < 3; ++p) {
            float f0 = f[0*3+p], f1 = f[1*3+p], f2 = f[2*3+p];
            float mx = fmaxf(f0, fmaxf(f1, f2));
            float e0 = expf(f0-mx), e1 = expf(f1-mx), e2 = expf(f2-mx);
            float inv = 1.f / (e0 + e1 + e2);
            prob[p*3+0] = e0*inv; prob[p*3+1] = e1*inv; prob[p*3+2] = e2*inv;
        }
    }
    __syncthreads();

    if (w < 3) {
        float p0 = prob[w*3+0], p1 = prob[w*3+1], p2 = prob[w*3+2];
#pragma unroll
        for (int i = 0; i < 18; ++i) bcol[i] = 0.f;
        if (lane < 18) {
            const float* V0 = logs + 2*324;
            const float* V1 = logs + 5*324;
            const float* V2 = logs + 8*324;
#pragma unroll
            for (int i = 0; i < 18; ++i) {
                int e = i*18 + lane;
                bcol[i] = p0*V0[e] + p1*V1[e] + p2*V2[e];
            }
        }
        float bound = 1e30f;
        if (lane < 18) {
            float rs = 0.f;
#pragma unroll
            for (int i = 0; i < 18; ++i) rs += fabsf(bcol[i]);
            float dg = bcol[lane];
            bound = dg - (rs - fabsf(dg));
        }
#pragma unroll
        for (int off = 16; off; off >>= 1) bound = fminf(bound, __shfl_xor_sync(0xffffffffu, bound, off));
        float alpha = fmaxf(0.f, -bound) + 1.0f;
        if (lane < 18) bcol[lane] += alpha;

        jacobi1s(bcol, sched, lane, NSWEEP2);

        float app = 0.f;
#pragma unroll
        for (int i = 0; i < 18; ++i) app = fmaf(bcol[i], bcol[i], app);
        float* St = ES + w*720;
        float* Bt = St + 360;
        if (lane < 18) {
            float lamS = sqrtf(app);
            float ev = fmaxf(lamS - alpha, LOG_RECT_EPS);
            float coef = ev / fmaxf(app, 1e-38f);
#pragma unroll
            for (int i = 0; i < 18; ++i) { St[i*20 + lane] = coef*bcol[i]; Bt[i*20 + lane] = bcol[i]; }
        }
        __syncwarp();
        for (int e = lane; e < 171; e += 32) {
            int i = 0, rem = e;
            while (rem >= 18 - i) { rem -= 18 - i; ++i; }
            int j = i + rem;
            const float4* Si = (const float4*)(St + i*20);
            const float4* Bj = (const float4*)(Bt + j*20);
            float s = 0.f;
#pragma unroll
            for (int m = 0; m < 4; ++m) {
                float4 a4 = Si[m], c4 = Bj[m];
                s += a4.x*c4.x + a4.y*c4.y + a4.z*c4.z + a4.w*c4.w;
            }
            s += St[i*20+16]*Bt[j*20+16] + St[i*20+17]*Bt[j*20+17];
            feat[w*171 + e] = s;
        }
    }
    __syncthreads();

    if (w < 4) {
        float acc = 0.f;
        for (int f = lane; f < 513; f += 32) acc = fmaf(lw[w*513 + f], feat[f], acc);
#pragma unroll
        for (int off = 16; off; off >>= 1) acc += __shfl_xor_sync(0xffffffffu, acc, off);
        if (lane == 0) out[b*4 + w] = acc + lb[w];
    }
}

// ---------------- launcher ----------------
extern "C" void kernel_launch(void* const* d_in, const int* in_sizes, int n_in,
                              void* d_out, int out_size) {
    const float* x   = (const float*)d_in[0];
    const float* w1  = (const float*)d_in[1];
    const float* b1  = (const float*)d_in[2];
    const float* g1  = (const float*)d_in[3];
    const float* be1 = (const float*)d_in[4];
    const float* w2  = (const float*)d_in[5];
    const float* b2  = (const float*)d_in[6];
    const float* g2  = (const float*)d_in[7];
    const float* Wq  = (const float*)d_in[9];
    const float* Wk  = (const float*)d_in[10];
    const float* Wv  = (const float*)d_in[11];
    const float* lw  = (const float*)d_in[12];
    const float* lb  = (const float*)d_in[13];

    size_t smem13 = (size_t)(C1*TPAD) * sizeof(float);
    cudaFuncSetAttribute(k13, cudaFuncAttributeMaxDynamicSharedMemorySize, (int)smem13);
    cudaFuncSetAttribute(k45, cudaFuncAttributeMaxDynamicSharedMemorySize, SMEM_BYTES);

    k0<<<B_, 256>>>(x);
    kred<<<275, 256>>>();
    kw<<<1, 256>>>(w1, b1, g1, be1, w2, b2);
    k13<<<B_, 288, smem13>>>(x);
    k45<<<B_, 288, SMEM_BYTES>>>(g2, Wq, Wk, Wv, lw, lb, (float*)d_out);
}